// round 17
// baseline (speedup 1.0000x reference)
#include <cuda_runtime.h>
#include <cuda_bf16.h>

// CaptionDetectionTargetLayer: B=8, N=4096, G=512, C=15
// Outputs (concat float32): rois[B,200,4] | deltas[B,200,4] | caps[B,200,15] | scores[B,200]

#define T_ROIS   200
#define POS_MAX  66
#define NB       4096
#define MAXG     512
#define ZL       8            // z-lanes per proposal (within warp)
#define GP       64           // gts per z-lane (512/8)
#define PPB      32           // proposals per block
#define K1_BLOCK 256          // PPB * ZL
#define K2_BLOCK 1024

// 0.5 - 2^-26: fdiv_rn(inter,uni) >= 0.5  <=>  inter >= THR*uni (exact in f64)
#define THR_EXACT 0.49999998509883880615234375

__device__ unsigned char g_flags[8 * NB];   // 0=invalid, 1=neg, 2=pos

// ---------------------------------------------------------------------------
// Kernel 1: per-proposal POSITIVE-FLAG pass only (no argmax). gt dim split
// across 8 lanes of a warp, STRIDED mapping j = jj*8 + z (conflict-free LDS).
// Per pair: t = inter - 0.5*uni (one FMA); t > eps*uni -> definitely pos,
// |t| <= eps*uni (rare) -> exact f64 threshold check. inter/uni use the
// reference's exact f32 op sequence, so the >=0.5 decision is bit-exact.
// Invalid gts stored as sentinel box (2,2,2,2)/area 0 -> inter=0, never pos.
// Extra block column zero-fills the output concurrently.
// ---------------------------------------------------------------------------
__global__ void iou_flag_kernel(const float4* __restrict__ proposals,
                                const float4* __restrict__ gt,
                                int N, int G, int C, int B,
                                float* __restrict__ out)
{
    const int b = blockIdx.y;

    if (blockIdx.x == gridDim.x - 1) {
        // zero-fill this image's output slices (harness poisons the buffer)
        float* rois    = out + (size_t)b * T_ROIS * 4;
        float* deltas  = out + (size_t)B * T_ROIS * 4 + (size_t)b * T_ROIS * 4;
        float* ocaps   = out + (size_t)2 * B * T_ROIS * 4 + (size_t)b * T_ROIS * C;
        float* oscores = out + (size_t)B * T_ROIS * (8 + C) + (size_t)b * T_ROIS;
        for (int k = threadIdx.x; k < T_ROIS * 4; k += K1_BLOCK) { rois[k] = 0.0f; deltas[k] = 0.0f; }
        for (int k = threadIdx.x; k < T_ROIS * C; k += K1_BLOCK) ocaps[k] = 0.0f;
        for (int k = threadIdx.x; k < T_ROIS;     k += K1_BLOCK) oscores[k] = 0.0f;
        return;
    }

    __shared__ float4 sg[MAXG];
    __shared__ float  sa2[MAXG];

    for (int j = threadIdx.x; j < G; j += K1_BLOCK) {
        float4 g = gt[(size_t)b * G + j];
        bool vg  = (fabsf(g.x) + fabsf(g.y) + fabsf(g.z) + fabsf(g.w)) > 0.0f;
        if (!vg) g = make_float4(2.0f, 2.0f, 2.0f, 2.0f);   // sentinel: inter=0
        sg[j]  = g;
        sa2[j] = vg ? (g.z - g.x) * (g.w - g.y) : 0.0f;
    }
    __syncthreads();

    const int z    = threadIdx.x & (ZL - 1);        // 0..7 within 8-lane group
    const int pl   = threadIdx.x >> 3;              // proposal-local 0..31
    const int lane = threadIdx.x & 31;
    const int i    = blockIdx.x * PPB + pl;

    float4 p  = proposals[(size_t)b * N + i];       // broadcast across 8 lanes
    float  a1 = (p.z - p.x) * (p.w - p.y);
    bool   vp = (fabsf(p.x) + fabsf(p.y) + fabsf(p.z) + fabsf(p.w)) > 0.0f;

    bool pos = false;

    #pragma unroll 4
    for (int jj = 0; jj < GP; ++jj) {
        int j = (jj << 3) + z;                      // strided: lanes -> consecutive
        float4 g  = sg[j];
        float  a2 = sa2[j];
        float y1 = fmaxf(p.x, g.x);
        float x1 = fmaxf(p.y, g.y);
        float y2 = fminf(p.z, g.z);
        float x2 = fminf(p.w, g.w);
        float inter = fmaxf(x2 - x1, 0.0f) * fmaxf(y2 - y1, 0.0f);
        float uni   = (a1 + a2) - inter;            // reference op order

        float t = __fmaf_rn(uni, -0.5f, inter);     // inter - uni/2
        float e = __fmul_rn(uni, 1e-6f);
        bool up = t > e;
        if (!up && t > -e) {
            // ambiguity band (rare): exact threshold, products exact in f64
            up = ((double)inter >= (double)uni * THR_EXACT);
        }
        pos |= up;
    }

    // OR across the 8 z-lanes of this proposal's group via one ballot
    unsigned bal = __ballot_sync(0xFFFFFFFFu, pos);
    bool grp_pos = ((bal >> (lane & 24)) & 0xFFu) != 0u;

    if (z == 0)
        g_flags[b * N + i] = vp ? (grp_pos ? 2 : 1) : 0;
}

// ---------------------------------------------------------------------------
// Kernel 2: per-image ordered compaction + argmax-for-positives + scatter.
// One block of 1024 threads per image. After staging, negatives scatter while
// all 32 warps compute argmax for the <=66 positive slots using the LITERAL
// reference arithmetic (__fdiv_rn per pair, strict >, min-idx tie =
// first occurrence) -- bit-exact. Then pos scatter + caption/score gather.
// ---------------------------------------------------------------------------
__global__ void select_kernel(const float4* __restrict__ proposals,
                              const float4* __restrict__ gt,
                              const int*    __restrict__ caps,
                              const float*  __restrict__ scores,
                              int N, int G, int C, int B,
                              float* __restrict__ out)
{
    const int b    = blockIdx.x;
    const int t    = threadIdx.x;
    const int lane = t & 31;
    const int wid  = t >> 5;

    // load 4 flags as one word; count pos/neg
    unsigned int fl4 = ((const unsigned int*)(g_flags + b * N))[t];
    unsigned char f[4];
    int pc = 0, nc = 0;
    #pragma unroll
    for (int k = 0; k < 4; ++k) {
        f[k] = (fl4 >> (8 * k)) & 0xFF;
        pc += (f[k] == 2);
        nc += (f[k] == 1);
    }

    // packed (pos<<16 | neg) inclusive warp scan
    int v = (pc << 16) | nc;
    int incl = v;
    #pragma unroll
    for (int off = 1; off < 32; off <<= 1) {
        int n = __shfl_up_sync(0xFFFFFFFFu, incl, off);
        if (lane >= off) incl += n;
    }

    __shared__ int swarp[33];
    if (lane == 31) swarp[wid] = incl;
    __syncthreads();
    if (wid == 0) {
        int wv = swarp[lane];
        int wincl = wv;
        #pragma unroll
        for (int off = 1; off < 32; off <<= 1) {
            int n = __shfl_up_sync(0xFFFFFFFFu, wincl, off);
            if (lane >= off) wincl += n;
        }
        swarp[lane] = wincl - wv;
        if (lane == 31) swarp[32] = wincl;
    }
    __syncthreads();

    int excl   = swarp[wid] + incl - v;
    int total  = swarp[32];
    int p_base = excl >> 16;
    int n_base = excl & 0xFFFF;
    int pos_total = total >> 16;
    int neg_total = total & 0xFFFF;

    int pos_cnt = min(pos_total, POS_MAX);
    // XLA div-by-const -> mul-by-reciprocal: 66*round(1/0.33)=199.99999347->200.0f
    float rcp = __fdiv_rn(1.0f, 0.33f);
    int neg_target = (int)__fmul_rn((float)pos_cnt, rcp) - pos_cnt;
    int neg_cnt = min(min(neg_target, neg_total), T_ROIS - pos_cnt);
    if (neg_cnt < 0) neg_cnt = 0;

    // stage selected roi indices (ascending order preserved)
    __shared__ int   spos[POS_MAX];
    __shared__ int   sneg[T_ROIS];
    __shared__ short sargm[POS_MAX];
    {
        int pr = p_base, nr = n_base;
        int base = t * 4;
        #pragma unroll
        for (int k = 0; k < 4; ++k) {
            int i = base + k;
            if (f[k] == 2) {
                if (pr < pos_cnt) spos[pr] = i;
                pr++;
            } else if (f[k] == 1) {
                if (nr < neg_cnt) sneg[nr] = i;
                nr++;
            }
        }
    }
    __syncthreads();

    // output sections
    float* rois    = out + (size_t)b * T_ROIS * 4;
    float* deltas  = out + (size_t)B * T_ROIS * 4 + (size_t)b * T_ROIS * 4;
    float* ocaps   = out + (size_t)2 * B * T_ROIS * 4 + (size_t)b * T_ROIS * C;
    float* oscores = out + (size_t)B * T_ROIS * (8 + C) + (size_t)b * T_ROIS;
    float4* rois4   = (float4*)rois;
    float4* deltas4 = (float4*)deltas;

    // negative roi scatter (no argmax dependency; overlaps with argmax below)
    if (t >= 512 && (t - 512) < neg_cnt) {
        int s = t - 512;
        int i = sneg[s];
        rois4[pos_cnt + s] = proposals[(size_t)b * N + i];
    }

    // argmax for positives: one warp per slot, literal reference arithmetic
    for (int s = wid; s < pos_cnt; s += 32) {
        int i = spos[s];
        float4 p = proposals[(size_t)b * N + i];    // broadcast load
        float a1 = (p.z - p.x) * (p.w - p.y);
        float best = -2.0f;
        int   bi   = 0;
        #pragma unroll 4
        for (int it = 0; it < MAXG / 32; ++it) {
            int j = it * 32 + lane;                 // coalesced gt loads
            float4 g = gt[(size_t)b * G + j];
            bool vg = (fabsf(g.x) + fabsf(g.y) + fabsf(g.z) + fabsf(g.w)) > 0.0f;
            float y1 = fmaxf(p.x, g.x);
            float x1 = fmaxf(p.y, g.y);
            float y2 = fminf(p.z, g.z);
            float x2 = fminf(p.w, g.w);
            float inter = fmaxf(x2 - x1, 0.0f) * fmaxf(y2 - y1, 0.0f);
            float uni   = (a1 + (g.z - g.x) * (g.w - g.y)) - inter;
            float d     = uni > 0.0f ? uni : 1.0f;
            float iou   = __fdiv_rn(inter, d);
            float m     = vg ? iou : -1.0f;
            if (m > best) { best = m; bi = j; }     // strict >: first occurrence
        }
        // merge across warp: max value, min index on ties
        #pragma unroll
        for (int off = 16; off; off >>= 1) {
            float ob = __shfl_xor_sync(0xFFFFFFFFu, best, off);
            int   oi = __shfl_xor_sync(0xFFFFFFFFu, bi,   off);
            if (ob > best || (ob == best && oi < bi)) { best = ob; bi = oi; }
        }
        if (lane == 0) sargm[s] = (short)bi;
    }
    __syncthreads();

    // positive roi + delta scatter (t < pos_cnt <= 66)
    if (t < pos_cnt) {
        int i = spos[t];
        float4 p = proposals[(size_t)b * N + i];
        int gi = sargm[t];
        float4 g = gt[(size_t)b * G + gi];

        rois4[t] = p;

        float h  = p.z - p.x, w  = p.w - p.y;
        float cy = p.x + 0.5f * h, cx = p.y + 0.5f * w;
        float gh = g.z - g.x, gw = g.w - g.y;
        float gcy = g.x + 0.5f * gh, gcx = g.y + 0.5f * gw;
        float4 d4;
        d4.x = __fdiv_rn(__fdiv_rn(gcy - cy, h), 0.1f);
        d4.y = __fdiv_rn(__fdiv_rn(gcx - cx, w), 0.1f);
        d4.z = __fdiv_rn(logf(__fdiv_rn(gh, h)), 0.2f);
        d4.w = __fdiv_rn(logf(__fdiv_rn(gw, w)), 0.2f);
        deltas4[t] = d4;
    }

    // caption + score gather: 16 elems per positive slot (c<15 cap, c==15 score)
    for (int idx = t; idx < pos_cnt * 16; idx += K2_BLOCK) {
        int slot = idx >> 4;
        int c    = idx & 15;
        int gi   = sargm[slot];
        if (c < C)
            ocaps[slot * C + c] = (float)caps[((size_t)b * G + gi) * C + c];
        else
            oscores[slot] = scores[(size_t)b * G + gi];
    }
}

// ---------------------------------------------------------------------------
extern "C" void kernel_launch(void* const* d_in, const int* in_sizes, int n_in,
                              void* d_out, int out_size)
{
    const float4* proposals = (const float4*)d_in[0];
    const float4* gt_boxes  = (const float4*)d_in[1];
    const int*    captions  = (const int*)  d_in[2];
    const float*  scores    = (const float*)d_in[3];
    float*        out       = (float*)d_out;

    const int N = NB;
    int B = in_sizes[0] / (4 * N);         // 8
    int G = in_sizes[3] / B;               // 512
    int C = in_sizes[2] / in_sizes[3];     // 15

    dim3 grid1(N / PPB + 1, B);            // +1 block column zero-fills output
    iou_flag_kernel<<<grid1, K1_BLOCK>>>(proposals, gt_boxes, N, G, C, B, out);

    select_kernel<<<B, K2_BLOCK>>>(proposals, gt_boxes, captions, scores,
                                   N, G, C, B, out);
}